// round 11
// baseline (speedup 1.0000x reference)
#include <cuda_runtime.h>
#include <math.h>

#define HOR   256
#define EPSV  0.001f

// ---------------- device-global weights ----------------
__device__ float g_C1T [64*64];
__device__ float g_FT  [64*64];
__device__ float g_D11T[64*64];
__device__ float g_B1T [64*64];
__device__ float g_B2T [32*64];
__device__ float g_D12T[32*64];
__device__ float g_E   [64*64];
__device__ float g_EinvT[64*64];
__device__ float g_il2 [64];
// fused weights: column-k layout, lane owns feature pair (2l,2l+1)
__device__ float4 g_XW[64*32];      // (M1'[2l][k], M1'[2l+1][k], M2[2l][k], M2[2l+1][k])
__device__ float4 g_UW[32*32];      // (D12'[2l][k], D12'[2l+1][k], B2[2l][k], B2[2l+1][k])
__device__ float4 g_WW[64*32];      // (D11'[2l][i], D11'[2l+1][i], B1[2l][i], B1[2l+1][i])
__device__ float  g_D21T[64*32];    // D21[f][i] at [i*32+f]
__device__ float  g_D22T[32*32];    // D22[f][k] at [k*32+f]
__device__ float  g_YWT [64*32];    // (C2@Einv)[f][k] at [k*32+f]

// ---------------- kernel 1: H blocks + transposes ----------------
__global__ void ren_precompute(const float* __restrict__ X, const float* __restrict__ Y,
                               const float* __restrict__ B2, const float* __restrict__ C2,
                               const float* __restrict__ D21, const float* __restrict__ D22,
                               const float* __restrict__ D12) {
    int gid = blockIdx.x * blockDim.x + threadIdx.x;
    if (gid >= 4096) return;
    int f = gid >> 6, k = gid & 63;

    float s11 = 0.f, s21 = 0.f, s22 = 0.f, s31 = 0.f, s32 = 0.f, s33 = 0.f;
    for (int j = 0; j < 192; j++) {
        const float* row = X + j * 192;
        float a0 = row[f], a1 = row[64 + f], a2 = row[128 + f];
        float b0 = row[k], b1 = row[64 + k], b2 = row[128 + k];
        s11 += a0 * b0; s21 += a1 * b0; s22 += a1 * b1;
        s31 += a2 * b0; s32 += a2 * b1; s33 += a2 * b2;
    }
    g_C1T [k*64 + f] = -s21;
    g_FT  [k*64 + f] =  s31;
    g_B1T [k*64 + f] =  s32;
    g_D11T[k*64 + f] = (k < f) ? -s22 : 0.f;

    float diag = (f == k) ? EPSV : 0.f;
    if (f == k) g_il2[f] = 5.7707803071388442f / (s22 + EPSV);   // 4*log2e/(s22+eps)
    g_E[f*64 + k] = 0.5f * ((s11 + diag) + (s33 + diag) + Y[f*64 + k] - Y[k*64 + f]);

    if (gid < 2048) {
        int ff = gid & 63, kk = gid >> 6;
        g_B2T [kk*64 + ff] = B2 [ff*32 + kk];
        g_D12T[kk*64 + ff] = D12[ff*32 + kk];
        int f2 = gid & 31, k2 = gid >> 5;
        g_D21T[k2*32 + f2] = D21[f2*64 + k2];
        g_YWT [k2*32 + f2] = C2 [f2*64 + k2];   // staging C2^T
    }
    if (gid < 1024) {
        int f3 = gid & 31, k3 = gid >> 5;
        g_D22T[k3*32 + f3] = D22[f3*32 + k3];
    }
}

// ---------------- kernel 2: Gauss-Jordan inversion of E ----------------
__global__ void ren_invert() {
    __shared__ float W[64 * 128];
    __shared__ int s_piv;
    int tid = threadIdx.x;

    for (int e = tid; e < 64 * 128; e += 256) {
        int r = e >> 7, c = e & 127;
        W[e] = (c < 64) ? g_E[r*64 + c] : ((c - 64 == r) ? 1.f : 0.f);
    }
    __syncthreads();

    for (int col = 0; col < 64; col++) {
        if (tid < 32) {
            int   r0 = col + tid;
            float b0 = (r0 < 64) ? fabsf(W[r0*128 + col]) : -1.f;
            int   r1 = r0 + 32;
            float b1 = (r1 < 64) ? fabsf(W[r1*128 + col]) : -1.f;
            if (b1 > b0) { b0 = b1; r0 = r1; }
            for (int off = 16; off > 0; off >>= 1) {
                float ob = __shfl_down_sync(0xffffffffu, b0, off);
                int   orr = __shfl_down_sync(0xffffffffu, r0, off);
                if (ob > b0) { b0 = ob; r0 = orr; }
            }
            if (tid == 0) s_piv = r0;
        }
        __syncthreads();
        int p = s_piv;
        if (p != col && tid < 128) {
            float tmp = W[col*128 + tid];
            W[col*128 + tid] = W[p*128 + tid];
            W[p*128 + tid] = tmp;
        }
        __syncthreads();
        float pivinv = 1.f / W[col*128 + col];
        __syncthreads();
        if (tid < 128) W[col*128 + tid] *= pivinv;
        __syncthreads();

        float fac[32];
        #pragma unroll
        for (int kk = 0; kk < 32; kk++) {
            int e = tid + kk * 256; int r = e >> 7;
            fac[kk] = (r == col) ? 0.f : W[r*128 + col];
        }
        __syncthreads();
        #pragma unroll
        for (int kk = 0; kk < 32; kk++) {
            int e = tid + kk * 256; int c = e & 127;
            W[e] -= fac[kk] * W[col*128 + c];
        }
        __syncthreads();
    }

    for (int e = tid; e < 4096; e += 256) {
        int f = e >> 6, k = e & 63;
        g_EinvT[k*64 + f] = W[f*128 + 64 + k];
    }
}

// ---------------- kernel 3: fuse Einv + il2 into weights ----------------
__global__ void ren_fuse() {
    __shared__ float sC2T[64*32];
    int tid = threadIdx.x;
    for (int i = tid; i < 2048; i += 256) sC2T[i] = g_YWT[i];
    __syncthreads();

    int id = blockIdx.x * blockDim.x + tid;
    if (id >= 4096) return;
    int f = id & 63, k = id >> 6;
    float il2f = g_il2[f];

    float m1 = 0.f, m2 = 0.f;
    for (int j = 0; j < 64; j++) {
        float e = g_EinvT[k*64 + j];
        m1 += g_C1T[j*64 + f] * e;
        m2 += g_FT [j*64 + f] * e;
    }
    float* xw = (float*)g_XW;
    int base = (k*32 + (f >> 1)) * 4 + (f & 1);
    xw[base]     = m1 * il2f;
    xw[base + 2] = m2;

    float* ww = (float*)g_WW;
    ww[base]     = g_D11T[k*64 + f] * il2f;
    ww[base + 2] = g_B1T [k*64 + f];

    if (k < 32) {
        float* uw = (float*)g_UW;
        uw[base]     = g_D12T[k*64 + f] * il2f;
        uw[base + 2] = g_B2T [k*64 + f];
    }
    if (f < 32) {
        float m3 = 0.f;
        for (int j = 0; j < 64; j++)
            m3 += sC2T[j*32 + f] * g_EinvT[k*64 + j];
        g_YWT[k*32 + f] = m3;
    }
}

// tanh of pre-scaled arg a = 2*log2e*z, returns tanh(z)
__device__ __forceinline__ float tanh_ex2(float a) {
    float e, r;
    asm("ex2.approx.f32 %0, %1;" : "=f"(e) : "f"(a));
    asm("rcp.approx.f32 %0, %1;" : "=f"(r) : "f"(e + 1.0f));
    return fmaf(-2.0f, r, 1.0f);
}

// ---------------- kernel 4: main — one warp handles TWO batch elements ----------------
__global__ void __launch_bounds__(128, 1)
ren_main(const float* __restrict__ u_in, float* __restrict__ out) {
    extern __shared__ float sm[];
    float4* sXW  = (float4*)sm;              // 2048 f4 (8192 f)
    float4* sUW  = (float4*)(sm + 8192);     // 1024 f4 (4096 f)
    float4* sWW  = (float4*)(sm + 12288);    // 2048 f4 (8192 f)
    float*  sD21 = sm + 20480;               // 2048
    float*  sD22 = sm + 22528;               // 1024
    float*  sYW  = sm + 23552;               // 2048  -> total 25600 f = 102400 B

    int tid = threadIdx.x;
    for (int i = tid; i < 2048; i += 128) { sXW[i] = g_XW[i]; sWW[i] = g_WW[i]; }
    for (int i = tid; i < 1024; i += 128) { sUW[i] = g_UW[i]; sD22[i] = g_D22T[i]; }
    for (int i = tid; i < 2048; i += 128) { sD21[i] = g_D21T[i]; sYW[i] = g_YWT[i]; }
    __syncthreads();

    int warp = tid >> 5, lane = tid & 31;
    int b0 = (blockIdx.x * 4 + warp) * 2;

    // per-lane coupling scalar d = D11'[2l+1][2l]
    float d = ((const float*)sWW)[260 * lane + 1];

    const float* uA = u_in + (size_t)b0 * (HOR * 32) + lane;
    const float* uB = uA + HOR * 32;
    float* oA = out + (size_t)b0 * (HOR * 32) + lane;
    float* oB = oA + HOR * 32;

    float2 tA = make_float2(0.f, 0.f);   // state t = E*x (pre-inverse), lane owns (2l,2l+1)
    float2 tB = make_float2(0.f, 0.f);
    float unA = uA[0], unB = uB[0];

    for (int t = 0; t < HOR; t++) {
        float ucA = unA, ucB = unB;
        if (t < HOR - 1) { unA = uA[(t + 1) * 32]; unB = uB[(t + 1) * 32]; }

        float2 preA = make_float2(0.f, 0.f), preB = make_float2(0.f, 0.f);
        float2 tvA  = make_float2(0.f, 0.f), tvB  = make_float2(0.f, 0.f);
        float  yaA = 0.f, yaB = 0.f;

        // ---- t-dots: pre += M1'·t ; tv += M2·t (t broadcast by shfl from owner lane) ----
        #pragma unroll
        for (int k = 0; k < 64; k++) {
            float sa = (k & 1) ? tA.y : tA.x;
            float sb = (k & 1) ? tB.y : tB.x;
            float ta = __shfl_sync(0xffffffffu, sa, k >> 1);
            float tb = __shfl_sync(0xffffffffu, sb, k >> 1);
            float4 w = sXW[k*32 + lane];
            preA.x = fmaf(w.x, ta, preA.x); preA.y = fmaf(w.y, ta, preA.y);
            tvA.x  = fmaf(w.z, ta, tvA.x);  tvA.y  = fmaf(w.w, ta, tvA.y);
            preB.x = fmaf(w.x, tb, preB.x); preB.y = fmaf(w.y, tb, preB.y);
            tvB.x  = fmaf(w.z, tb, tvB.x);  tvB.y  = fmaf(w.w, tb, tvB.y);
        }
        // ---- u-dots ----
        #pragma unroll
        for (int k = 0; k < 32; k++) {
            float ua = __shfl_sync(0xffffffffu, ucA, k);
            float ub = __shfl_sync(0xffffffffu, ucB, k);
            float4 w = sUW[k*32 + lane];
            preA.x = fmaf(w.x, ua, preA.x); preA.y = fmaf(w.y, ua, preA.y);
            tvA.x  = fmaf(w.z, ua, tvA.x);  tvA.y  = fmaf(w.w, ua, tvA.y);
            preB.x = fmaf(w.x, ub, preB.x); preB.y = fmaf(w.y, ub, preB.y);
            tvB.x  = fmaf(w.z, ub, tvB.x);  tvB.y  = fmaf(w.w, ub, tvB.y);
            float dd = sD22[k*32 + lane];
            yaA = fmaf(dd, ua, yaA); yaB = fmaf(dd, ub, yaB);
        }
        // ---- w recurrence: 32 pair iterations; owner lane computes both tanhs ----
        #pragma unroll
        for (int m = 0; m < 32; m++) {
            // speculative in all lanes; only lane m's values are selected
            float waA = tanh_ex2(preA.x);
            float wbA = tanh_ex2(fmaf(d, waA, preA.y));
            float waB = tanh_ex2(preB.x);
            float wbB = tanh_ex2(fmaf(d, waB, preB.y));
            waA = __shfl_sync(0xffffffffu, waA, m);
            wbA = __shfl_sync(0xffffffffu, wbA, m);
            waB = __shfl_sync(0xffffffffu, waB, m);
            wbB = __shfl_sync(0xffffffffu, wbB, m);

            float4 wa4 = sWW[(2*m)    *32 + lane];
            float4 wb4 = sWW[(2*m + 1)*32 + lane];
            preA.x = fmaf(wa4.x, waA, fmaf(wb4.x, wbA, preA.x));
            preA.y = fmaf(wa4.y, waA, fmaf(wb4.y, wbA, preA.y));
            tvA.x  = fmaf(wa4.z, waA, fmaf(wb4.z, wbA, tvA.x));
            tvA.y  = fmaf(wa4.w, waA, fmaf(wb4.w, wbA, tvA.y));
            preB.x = fmaf(wa4.x, waB, fmaf(wb4.x, wbB, preB.x));
            preB.y = fmaf(wa4.y, waB, fmaf(wb4.y, wbB, preB.y));
            tvB.x  = fmaf(wa4.z, waB, fmaf(wb4.z, wbB, tvB.x));
            tvB.y  = fmaf(wa4.w, waB, fmaf(wb4.w, wbB, tvB.y));

            float da = sD21[(2*m)*32 + lane], db = sD21[(2*m+1)*32 + lane];
            yaA = fmaf(da, waA, fmaf(db, wbA, yaA));
            yaB = fmaf(da, waB, fmaf(db, wbB, yaB));
        }
        tA = tvA; tB = tvB;
        // ---- y = (C2·Einv)·t_new + accumulated (D21 w + D22 u) ----
        #pragma unroll
        for (int k = 0; k < 64; k++) {
            float sa = (k & 1) ? tA.y : tA.x;
            float sb = (k & 1) ? tB.y : tB.x;
            float ta = __shfl_sync(0xffffffffu, sa, k >> 1);
            float tb = __shfl_sync(0xffffffffu, sb, k >> 1);
            float c = sYW[k*32 + lane];
            yaA = fmaf(c, ta, yaA); yaB = fmaf(c, tb, yaB);
        }
        oA[t * 32] = yaA;
        oB[t * 32] = yaB;
    }
}

// ---------------- launch ----------------
extern "C" void kernel_launch(void* const* d_in, const int* in_sizes, int n_in,
                              void* d_out, int out_size) {
    const float* u_in = (const float*)d_in[0];
    const float* X    = (const float*)d_in[1];
    const float* Y    = (const float*)d_in[2];
    const float* B2   = (const float*)d_in[3];
    const float* C2   = (const float*)d_in[4];
    const float* D21  = (const float*)d_in[5];
    const float* D22  = (const float*)d_in[6];
    const float* D12  = (const float*)d_in[7];
    float* out = (float*)d_out;

    (void)in_sizes; (void)n_in; (void)out_size;

    cudaFuncSetAttribute(ren_main, cudaFuncAttributeMaxDynamicSharedMemorySize, 102400);

    ren_precompute<<<32, 128>>>(X, Y, B2, C2, D21, D22, D12);
    ren_invert<<<1, 256>>>();
    ren_fuse<<<16, 256>>>();
    ren_main<<<128, 128, 102400>>>(u_in, out);
}

// round 12
// speedup vs baseline: 1.0053x; 1.0053x over previous
#include <cuda_runtime.h>
#include <math.h>

#define HOR   256
#define EPSV  0.001f

// ---------------- device-global weights ----------------
__device__ float g_C1T [64*64];
__device__ float g_FT  [64*64];
__device__ float g_D11T[64*64];
__device__ float g_B1T [64*64];
__device__ float g_B2T [32*64];
__device__ float g_D12T[32*64];
__device__ float g_E   [64*64];
__device__ float g_EinvT[64*64];
__device__ float g_il2 [64];
// fused weights: column-k layout, lane owns feature pair (2l,2l+1)
__device__ float4 g_XW[64*32];      // (M1'[2l][k], M1'[2l+1][k], M2[2l][k], M2[2l+1][k])
__device__ float4 g_UW[32*32];      // (D12'[2l][k], D12'[2l+1][k], B2[2l][k], B2[2l+1][k])
__device__ float4 g_WW[64*32];      // (D11'[2l][i], D11'[2l+1][i], B1[2l][i], B1[2l+1][i])
__device__ float  g_D21T[64*32];    // D21[f][i] at [i*32+f]
__device__ float  g_D22T[32*32];    // D22[f][k] at [k*32+f]
__device__ float  g_YWT [64*32];    // (C2@Einv)[f][k] at [k*32+f]

// ---------------- kernel 1: H blocks + transposes ----------------
__global__ void ren_precompute(const float* __restrict__ X, const float* __restrict__ Y,
                               const float* __restrict__ B2, const float* __restrict__ C2,
                               const float* __restrict__ D21, const float* __restrict__ D22,
                               const float* __restrict__ D12) {
    int gid = blockIdx.x * blockDim.x + threadIdx.x;
    if (gid >= 4096) return;
    int f = gid >> 6, k = gid & 63;

    float s11 = 0.f, s21 = 0.f, s22 = 0.f, s31 = 0.f, s32 = 0.f, s33 = 0.f;
    for (int j = 0; j < 192; j++) {
        const float* row = X + j * 192;
        float a0 = row[f], a1 = row[64 + f], a2 = row[128 + f];
        float b0 = row[k], b1 = row[64 + k], b2 = row[128 + k];
        s11 += a0 * b0; s21 += a1 * b0; s22 += a1 * b1;
        s31 += a2 * b0; s32 += a2 * b1; s33 += a2 * b2;
    }
    g_C1T [k*64 + f] = -s21;
    g_FT  [k*64 + f] =  s31;
    g_B1T [k*64 + f] =  s32;
    g_D11T[k*64 + f] = (k < f) ? -s22 : 0.f;

    float diag = (f == k) ? EPSV : 0.f;
    if (f == k) g_il2[f] = 5.7707803071388442f / (s22 + EPSV);   // 4*log2e/(s22+eps)
    g_E[f*64 + k] = 0.5f * ((s11 + diag) + (s33 + diag) + Y[f*64 + k] - Y[k*64 + f]);

    if (gid < 2048) {
        int ff = gid & 63, kk = gid >> 6;
        g_B2T [kk*64 + ff] = B2 [ff*32 + kk];
        g_D12T[kk*64 + ff] = D12[ff*32 + kk];
        int f2 = gid & 31, k2 = gid >> 5;
        g_D21T[k2*32 + f2] = D21[f2*64 + k2];
        g_YWT [k2*32 + f2] = C2 [f2*64 + k2];   // staging C2^T
    }
    if (gid < 1024) {
        int f3 = gid & 31, k3 = gid >> 5;
        g_D22T[k3*32 + f3] = D22[f3*32 + k3];
    }
}

// ---------------- kernel 2: Gauss-Jordan inversion of E ----------------
__global__ void ren_invert() {
    __shared__ float W[64 * 128];
    __shared__ int s_piv;
    int tid = threadIdx.x;

    for (int e = tid; e < 64 * 128; e += 256) {
        int r = e >> 7, c = e & 127;
        W[e] = (c < 64) ? g_E[r*64 + c] : ((c - 64 == r) ? 1.f : 0.f);
    }
    __syncthreads();

    for (int col = 0; col < 64; col++) {
        if (tid < 32) {
            int   r0 = col + tid;
            float b0 = (r0 < 64) ? fabsf(W[r0*128 + col]) : -1.f;
            int   r1 = r0 + 32;
            float b1 = (r1 < 64) ? fabsf(W[r1*128 + col]) : -1.f;
            if (b1 > b0) { b0 = b1; r0 = r1; }
            for (int off = 16; off > 0; off >>= 1) {
                float ob = __shfl_down_sync(0xffffffffu, b0, off);
                int   orr = __shfl_down_sync(0xffffffffu, r0, off);
                if (ob > b0) { b0 = ob; r0 = orr; }
            }
            if (tid == 0) s_piv = r0;
        }
        __syncthreads();
        int p = s_piv;
        if (p != col && tid < 128) {
            float tmp = W[col*128 + tid];
            W[col*128 + tid] = W[p*128 + tid];
            W[p*128 + tid] = tmp;
        }
        __syncthreads();
        float pivinv = 1.f / W[col*128 + col];
        __syncthreads();
        if (tid < 128) W[col*128 + tid] *= pivinv;
        __syncthreads();

        float fac[32];
        #pragma unroll
        for (int kk = 0; kk < 32; kk++) {
            int e = tid + kk * 256; int r = e >> 7;
            fac[kk] = (r == col) ? 0.f : W[r*128 + col];
        }
        __syncthreads();
        #pragma unroll
        for (int kk = 0; kk < 32; kk++) {
            int e = tid + kk * 256; int c = e & 127;
            W[e] -= fac[kk] * W[col*128 + c];
        }
        __syncthreads();
    }

    for (int e = tid; e < 4096; e += 256) {
        int f = e >> 6, k = e & 63;
        g_EinvT[k*64 + f] = W[f*128 + 64 + k];
    }
}

// ---------------- kernel 3: fuse Einv + il2 into weights ----------------
__global__ void ren_fuse() {
    __shared__ float sC2T[64*32];
    int tid = threadIdx.x;
    for (int i = tid; i < 2048; i += 256) sC2T[i] = g_YWT[i];
    __syncthreads();

    int id = blockIdx.x * blockDim.x + tid;
    if (id >= 4096) return;
    int f = id & 63, k = id >> 6;
    float il2f = g_il2[f];

    float m1 = 0.f, m2 = 0.f;
    for (int j = 0; j < 64; j++) {
        float e = g_EinvT[k*64 + j];
        m1 += g_C1T[j*64 + f] * e;
        m2 += g_FT [j*64 + f] * e;
    }
    float* xw = (float*)g_XW;
    int base = (k*32 + (f >> 1)) * 4 + (f & 1);
    xw[base]     = m1 * il2f;
    xw[base + 2] = m2;

    float* ww = (float*)g_WW;
    ww[base]     = g_D11T[k*64 + f] * il2f;
    ww[base + 2] = g_B1T [k*64 + f];

    if (k < 32) {
        float* uw = (float*)g_UW;
        uw[base]     = g_D12T[k*64 + f] * il2f;
        uw[base + 2] = g_B2T [k*64 + f];
    }
    if (f < 32) {
        float m3 = 0.f;
        for (int j = 0; j < 64; j++)
            m3 += sC2T[j*32 + f] * g_EinvT[k*64 + j];
        g_YWT[k*32 + f] = m3;
    }
}

// tanh of pre-scaled arg a = 2*log2e*z, returns tanh(z)
__device__ __forceinline__ float tanh_ex2(float a) {
    float e, r;
    asm("ex2.approx.f32 %0, %1;" : "=f"(e) : "f"(a));
    asm("rcp.approx.f32 %0, %1;" : "=f"(r) : "f"(e + 1.0f));
    return fmaf(-2.0f, r, 1.0f);
}

// ---------------- kernel 4: main — one warp handles TWO batch elements ----------------
__global__ void __launch_bounds__(128, 1)
ren_main(const float* __restrict__ u_in, float* __restrict__ out) {
    extern __shared__ float sm[];
    float4* sXW  = (float4*)sm;              // 2048 f4 (8192 f)
    float4* sUW  = (float4*)(sm + 8192);     // 1024 f4 (4096 f)
    float4* sWW  = (float4*)(sm + 12288);    // 2048 f4 (8192 f)
    float*  sD21 = sm + 20480;               // 2048
    float*  sD22 = sm + 22528;               // 1024
    float*  sYW  = sm + 23552;               // 2048  -> total 25600 f = 102400 B

    int tid = threadIdx.x;
    for (int i = tid; i < 2048; i += 128) { sXW[i] = g_XW[i]; sWW[i] = g_WW[i]; }
    for (int i = tid; i < 1024; i += 128) { sUW[i] = g_UW[i]; sD22[i] = g_D22T[i]; }
    for (int i = tid; i < 2048; i += 128) { sD21[i] = g_D21T[i]; sYW[i] = g_YWT[i]; }
    __syncthreads();

    int warp = tid >> 5, lane = tid & 31;
    int b0 = (blockIdx.x * 4 + warp) * 2;

    // per-lane coupling scalar d = D11'[2l+1][2l]
    float d = ((const float*)sWW)[260 * lane + 1];

    const float* uA = u_in + (size_t)b0 * (HOR * 32) + lane;
    const float* uB = uA + HOR * 32;
    float* oA = out + (size_t)b0 * (HOR * 32) + lane;
    float* oB = oA + HOR * 32;

    float2 tA = make_float2(0.f, 0.f);   // state t = E*x (pre-inverse), lane owns (2l,2l+1)
    float2 tB = make_float2(0.f, 0.f);
    float unA = uA[0], unB = uB[0];

    for (int t = 0; t < HOR; t++) {
        float ucA = unA, ucB = unB;
        if (t < HOR - 1) { unA = uA[(t + 1) * 32]; unB = uB[(t + 1) * 32]; }

        float2 preA = make_float2(0.f, 0.f), preB = make_float2(0.f, 0.f);
        float2 tvA  = make_float2(0.f, 0.f), tvB  = make_float2(0.f, 0.f);
        float  yaA = 0.f, yaB = 0.f;

        // ---- t-dots: pre += M1'·t ; tv += M2·t (t broadcast by shfl from owner lane) ----
        #pragma unroll
        for (int k = 0; k < 64; k++) {
            float sa = (k & 1) ? tA.y : tA.x;
            float sb = (k & 1) ? tB.y : tB.x;
            float ta = __shfl_sync(0xffffffffu, sa, k >> 1);
            float tb = __shfl_sync(0xffffffffu, sb, k >> 1);
            float4 w = sXW[k*32 + lane];
            preA.x = fmaf(w.x, ta, preA.x); preA.y = fmaf(w.y, ta, preA.y);
            tvA.x  = fmaf(w.z, ta, tvA.x);  tvA.y  = fmaf(w.w, ta, tvA.y);
            preB.x = fmaf(w.x, tb, preB.x); preB.y = fmaf(w.y, tb, preB.y);
            tvB.x  = fmaf(w.z, tb, tvB.x);  tvB.y  = fmaf(w.w, tb, tvB.y);
        }
        // ---- u-dots ----
        #pragma unroll
        for (int k = 0; k < 32; k++) {
            float ua = __shfl_sync(0xffffffffu, ucA, k);
            float ub = __shfl_sync(0xffffffffu, ucB, k);
            float4 w = sUW[k*32 + lane];
            preA.x = fmaf(w.x, ua, preA.x); preA.y = fmaf(w.y, ua, preA.y);
            tvA.x  = fmaf(w.z, ua, tvA.x);  tvA.y  = fmaf(w.w, ua, tvA.y);
            preB.x = fmaf(w.x, ub, preB.x); preB.y = fmaf(w.y, ub, preB.y);
            tvB.x  = fmaf(w.z, ub, tvB.x);  tvB.y  = fmaf(w.w, ub, tvB.y);
            float dd = sD22[k*32 + lane];
            yaA = fmaf(dd, ua, yaA); yaB = fmaf(dd, ub, yaB);
        }
        // ---- w recurrence: 32 pair iterations; owner lane computes both tanhs ----
        #pragma unroll
        for (int m = 0; m < 32; m++) {
            // speculative in all lanes; only lane m's values are selected
            float waA = tanh_ex2(preA.x);
            float wbA = tanh_ex2(fmaf(d, waA, preA.y));
            float waB = tanh_ex2(preB.x);
            float wbB = tanh_ex2(fmaf(d, waB, preB.y));
            waA = __shfl_sync(0xffffffffu, waA, m);
            wbA = __shfl_sync(0xffffffffu, wbA, m);
            waB = __shfl_sync(0xffffffffu, waB, m);
            wbB = __shfl_sync(0xffffffffu, wbB, m);

            float4 wa4 = sWW[(2*m)    *32 + lane];
            float4 wb4 = sWW[(2*m + 1)*32 + lane];
            preA.x = fmaf(wa4.x, waA, fmaf(wb4.x, wbA, preA.x));
            preA.y = fmaf(wa4.y, waA, fmaf(wb4.y, wbA, preA.y));
            tvA.x  = fmaf(wa4.z, waA, fmaf(wb4.z, wbA, tvA.x));
            tvA.y  = fmaf(wa4.w, waA, fmaf(wb4.w, wbA, tvA.y));
            preB.x = fmaf(wa4.x, waB, fmaf(wb4.x, wbB, preB.x));
            preB.y = fmaf(wa4.y, waB, fmaf(wb4.y, wbB, preB.y));
            tvB.x  = fmaf(wa4.z, waB, fmaf(wb4.z, wbB, tvB.x));
            tvB.y  = fmaf(wa4.w, waB, fmaf(wb4.w, wbB, tvB.y));

            float da = sD21[(2*m)*32 + lane], db = sD21[(2*m+1)*32 + lane];
            yaA = fmaf(da, waA, fmaf(db, wbA, yaA));
            yaB = fmaf(da, waB, fmaf(db, wbB, yaB));
        }
        tA = tvA; tB = tvB;
        // ---- y = (C2·Einv)·t_new + accumulated (D21 w + D22 u) ----
        #pragma unroll
        for (int k = 0; k < 64; k++) {
            float sa = (k & 1) ? tA.y : tA.x;
            float sb = (k & 1) ? tB.y : tB.x;
            float ta = __shfl_sync(0xffffffffu, sa, k >> 1);
            float tb = __shfl_sync(0xffffffffu, sb, k >> 1);
            float c = sYW[k*32 + lane];
            yaA = fmaf(c, ta, yaA); yaB = fmaf(c, tb, yaB);
        }
        oA[t * 32] = yaA;
        oB[t * 32] = yaB;
    }
}

// ---------------- launch ----------------
extern "C" void kernel_launch(void* const* d_in, const int* in_sizes, int n_in,
                              void* d_out, int out_size) {
    const float* u_in = (const float*)d_in[0];
    const float* X    = (const float*)d_in[1];
    const float* Y    = (const float*)d_in[2];
    const float* B2   = (const float*)d_in[3];
    const float* C2   = (const float*)d_in[4];
    const float* D21  = (const float*)d_in[5];
    const float* D22  = (const float*)d_in[6];
    const float* D12  = (const float*)d_in[7];
    float* out = (float*)d_out;

    (void)in_sizes; (void)n_in; (void)out_size;

    cudaFuncSetAttribute(ren_main, cudaFuncAttributeMaxDynamicSharedMemorySize, 102400);

    ren_precompute<<<32, 128>>>(X, Y, B2, C2, D21, D22, D12);
    ren_invert<<<1, 256>>>();
    ren_fuse<<<16, 256>>>();
    ren_main<<<128, 128, 102400>>>(u_in, out);
}

// round 13
// speedup vs baseline: 1.0065x; 1.0012x over previous
#include <cuda_runtime.h>
#include <math.h>

#define HOR   256
#define EPSV  0.001f

// ---------------- device-global weights ----------------
__device__ float g_C1T [64*64];
__device__ float g_FT  [64*64];
__device__ float g_D11T[64*64];
__device__ float g_B1T [64*64];
__device__ float g_B2T [32*64];
__device__ float g_D12T[32*64];
__device__ float g_E   [64*64];
__device__ float g_EinvT[64*64];
__device__ float g_il2 [64];
// fused weights: column-k layout, lane owns feature pair (2l,2l+1)
__device__ float4 g_XW[64*32];      // (M1'[2l][k], M1'[2l+1][k], M2[2l][k], M2[2l+1][k])
__device__ float4 g_UW[32*32];      // (D12'[2l][k], D12'[2l+1][k], B2[2l][k], B2[2l+1][k])
__device__ float4 g_WW[64*32];      // (D11'[2l][i], D11'[2l+1][i], B1[2l][i], B1[2l+1][i])
__device__ float  g_D21T[64*32];    // D21[f][i] at [i*32+f]
__device__ float  g_D22T[32*32];    // D22[f][k] at [k*32+f]
__device__ float  g_YWT [64*32];    // (C2@Einv)[f][k] at [k*32+f]

// ---------------- kernel 1: H blocks + transposes ----------------
__global__ void ren_precompute(const float* __restrict__ X, const float* __restrict__ Y,
                               const float* __restrict__ B2, const float* __restrict__ C2,
                               const float* __restrict__ D21, const float* __restrict__ D22,
                               const float* __restrict__ D12) {
    int gid = blockIdx.x * blockDim.x + threadIdx.x;
    if (gid >= 4096) return;
    int f = gid >> 6, k = gid & 63;

    float s11 = 0.f, s21 = 0.f, s22 = 0.f, s31 = 0.f, s32 = 0.f, s33 = 0.f;
    for (int j = 0; j < 192; j++) {
        const float* row = X + j * 192;
        float a0 = row[f], a1 = row[64 + f], a2 = row[128 + f];
        float b0 = row[k], b1 = row[64 + k], b2 = row[128 + k];
        s11 += a0 * b0; s21 += a1 * b0; s22 += a1 * b1;
        s31 += a2 * b0; s32 += a2 * b1; s33 += a2 * b2;
    }
    g_C1T [k*64 + f] = -s21;
    g_FT  [k*64 + f] =  s31;
    g_B1T [k*64 + f] =  s32;
    g_D11T[k*64 + f] = (k < f) ? -s22 : 0.f;

    float diag = (f == k) ? EPSV : 0.f;
    if (f == k) g_il2[f] = 5.7707803071388442f / (s22 + EPSV);   // 4*log2e/(s22+eps)
    g_E[f*64 + k] = 0.5f * ((s11 + diag) + (s33 + diag) + Y[f*64 + k] - Y[k*64 + f]);

    if (gid < 2048) {
        int ff = gid & 63, kk = gid >> 6;
        g_B2T [kk*64 + ff] = B2 [ff*32 + kk];
        g_D12T[kk*64 + ff] = D12[ff*32 + kk];
        int f2 = gid & 31, k2 = gid >> 5;
        g_D21T[k2*32 + f2] = D21[f2*64 + k2];
        g_YWT [k2*32 + f2] = C2 [f2*64 + k2];   // staging C2^T
    }
    if (gid < 1024) {
        int f3 = gid & 31, k3 = gid >> 5;
        g_D22T[k3*32 + f3] = D22[f3*32 + k3];
    }
}

// ---------------- kernel 2: Gauss-Jordan inversion of E ----------------
__global__ void ren_invert() {
    __shared__ float W[64 * 128];
    __shared__ int s_piv;
    int tid = threadIdx.x;

    for (int e = tid; e < 64 * 128; e += 256) {
        int r = e >> 7, c = e & 127;
        W[e] = (c < 64) ? g_E[r*64 + c] : ((c - 64 == r) ? 1.f : 0.f);
    }
    __syncthreads();

    for (int col = 0; col < 64; col++) {
        if (tid < 32) {
            int   r0 = col + tid;
            float b0 = (r0 < 64) ? fabsf(W[r0*128 + col]) : -1.f;
            int   r1 = r0 + 32;
            float b1 = (r1 < 64) ? fabsf(W[r1*128 + col]) : -1.f;
            if (b1 > b0) { b0 = b1; r0 = r1; }
            for (int off = 16; off > 0; off >>= 1) {
                float ob = __shfl_down_sync(0xffffffffu, b0, off);
                int   orr = __shfl_down_sync(0xffffffffu, r0, off);
                if (ob > b0) { b0 = ob; r0 = orr; }
            }
            if (tid == 0) s_piv = r0;
        }
        __syncthreads();
        int p = s_piv;
        if (p != col && tid < 128) {
            float tmp = W[col*128 + tid];
            W[col*128 + tid] = W[p*128 + tid];
            W[p*128 + tid] = tmp;
        }
        __syncthreads();
        float pivinv = 1.f / W[col*128 + col];
        __syncthreads();
        if (tid < 128) W[col*128 + tid] *= pivinv;
        __syncthreads();

        float fac[32];
        #pragma unroll
        for (int kk = 0; kk < 32; kk++) {
            int e = tid + kk * 256; int r = e >> 7;
            fac[kk] = (r == col) ? 0.f : W[r*128 + col];
        }
        __syncthreads();
        #pragma unroll
        for (int kk = 0; kk < 32; kk++) {
            int e = tid + kk * 256; int c = e & 127;
            W[e] -= fac[kk] * W[col*128 + c];
        }
        __syncthreads();
    }

    for (int e = tid; e < 4096; e += 256) {
        int f = e >> 6, k = e & 63;
        g_EinvT[k*64 + f] = W[f*128 + 64 + k];
    }
}

// ---------------- kernel 3: fuse Einv + il2 into weights ----------------
__global__ void ren_fuse() {
    __shared__ float sC2T[64*32];
    int tid = threadIdx.x;
    for (int i = tid; i < 2048; i += 256) sC2T[i] = g_YWT[i];
    __syncthreads();

    int id = blockIdx.x * blockDim.x + tid;
    if (id >= 4096) return;
    int f = id & 63, k = id >> 6;
    float il2f = g_il2[f];

    float m1 = 0.f, m2 = 0.f;
    for (int j = 0; j < 64; j++) {
        float e = g_EinvT[k*64 + j];
        m1 += g_C1T[j*64 + f] * e;
        m2 += g_FT [j*64 + f] * e;
    }
    float* xw = (float*)g_XW;
    int base = (k*32 + (f >> 1)) * 4 + (f & 1);
    xw[base]     = m1 * il2f;
    xw[base + 2] = m2;

    float* ww = (float*)g_WW;
    ww[base]     = g_D11T[k*64 + f] * il2f;
    ww[base + 2] = g_B1T [k*64 + f];

    if (k < 32) {
        float* uw = (float*)g_UW;
        uw[base]     = g_D12T[k*64 + f] * il2f;
        uw[base + 2] = g_B2T [k*64 + f];
    }
    if (f < 32) {
        float m3 = 0.f;
        for (int j = 0; j < 64; j++)
            m3 += sC2T[j*32 + f] * g_EinvT[k*64 + j];
        g_YWT[k*32 + f] = m3;
    }
}

// tanh of pre-scaled arg a = 2*log2e*z, returns tanh(z)
__device__ __forceinline__ float tanh_ex2(float a) {
    float e, r;
    asm("ex2.approx.f32 %0, %1;" : "=f"(e) : "f"(a));
    asm("rcp.approx.f32 %0, %1;" : "=f"(r) : "f"(e + 1.0f));
    return fmaf(-2.0f, r, 1.0f);
}

// ---------------- kernel 4: main — one warp handles TWO batch elements ----------------
__global__ void __launch_bounds__(128, 1)
ren_main(const float* __restrict__ u_in, float* __restrict__ out) {
    extern __shared__ float sm[];
    float4* sXW  = (float4*)sm;              // 2048 f4 (8192 f)
    float4* sUW  = (float4*)(sm + 8192);     // 1024 f4 (4096 f)
    float4* sWW  = (float4*)(sm + 12288);    // 2048 f4 (8192 f)
    float*  sD21 = sm + 20480;               // 2048
    float*  sD22 = sm + 22528;               // 1024
    float*  sYW  = sm + 23552;               // 2048  -> total 25600 f = 102400 B

    int tid = threadIdx.x;
    for (int i = tid; i < 2048; i += 128) { sXW[i] = g_XW[i]; sWW[i] = g_WW[i]; }
    for (int i = tid; i < 1024; i += 128) { sUW[i] = g_UW[i]; sD22[i] = g_D22T[i]; }
    for (int i = tid; i < 2048; i += 128) { sD21[i] = g_D21T[i]; sYW[i] = g_YWT[i]; }
    __syncthreads();

    int warp = tid >> 5, lane = tid & 31;
    int b0 = (blockIdx.x * 4 + warp) * 2;

    // per-lane coupling scalar d = D11'[2l+1][2l]
    float d = ((const float*)sWW)[260 * lane + 1];

    const float* uA = u_in + (size_t)b0 * (HOR * 32) + lane;
    const float* uB = uA + HOR * 32;
    float* oA = out + (size_t)b0 * (HOR * 32) + lane;
    float* oB = oA + HOR * 32;

    float2 tA = make_float2(0.f, 0.f);   // state t = E*x (pre-inverse), lane owns (2l,2l+1)
    float2 tB = make_float2(0.f, 0.f);
    float unA = uA[0], unB = uB[0];

    for (int t = 0; t < HOR; t++) {
        float ucA = unA, ucB = unB;
        if (t < HOR - 1) { unA = uA[(t + 1) * 32]; unB = uB[(t + 1) * 32]; }

        float2 preA = make_float2(0.f, 0.f), preB = make_float2(0.f, 0.f);
        float2 tvA  = make_float2(0.f, 0.f), tvB  = make_float2(0.f, 0.f);
        float  yaA = 0.f, yaB = 0.f;

        // ---- t-dots: pre += M1'·t ; tv += M2·t (t broadcast by shfl from owner lane) ----
        #pragma unroll
        for (int k = 0; k < 64; k++) {
            float sa = (k & 1) ? tA.y : tA.x;
            float sb = (k & 1) ? tB.y : tB.x;
            float ta = __shfl_sync(0xffffffffu, sa, k >> 1);
            float tb = __shfl_sync(0xffffffffu, sb, k >> 1);
            float4 w = sXW[k*32 + lane];
            preA.x = fmaf(w.x, ta, preA.x); preA.y = fmaf(w.y, ta, preA.y);
            tvA.x  = fmaf(w.z, ta, tvA.x);  tvA.y  = fmaf(w.w, ta, tvA.y);
            preB.x = fmaf(w.x, tb, preB.x); preB.y = fmaf(w.y, tb, preB.y);
            tvB.x  = fmaf(w.z, tb, tvB.x);  tvB.y  = fmaf(w.w, tb, tvB.y);
        }
        // ---- u-dots ----
        #pragma unroll
        for (int k = 0; k < 32; k++) {
            float ua = __shfl_sync(0xffffffffu, ucA, k);
            float ub = __shfl_sync(0xffffffffu, ucB, k);
            float4 w = sUW[k*32 + lane];
            preA.x = fmaf(w.x, ua, preA.x); preA.y = fmaf(w.y, ua, preA.y);
            tvA.x  = fmaf(w.z, ua, tvA.x);  tvA.y  = fmaf(w.w, ua, tvA.y);
            preB.x = fmaf(w.x, ub, preB.x); preB.y = fmaf(w.y, ub, preB.y);
            tvB.x  = fmaf(w.z, ub, tvB.x);  tvB.y  = fmaf(w.w, ub, tvB.y);
            float dd = sD22[k*32 + lane];
            yaA = fmaf(dd, ua, yaA); yaB = fmaf(dd, ub, yaB);
        }
        // ---- w recurrence: 32 pair iterations; owner lane computes both tanhs ----
        #pragma unroll
        for (int m = 0; m < 32; m++) {
            // speculative in all lanes; only lane m's values are selected
            float waA = tanh_ex2(preA.x);
            float wbA = tanh_ex2(fmaf(d, waA, preA.y));
            float waB = tanh_ex2(preB.x);
            float wbB = tanh_ex2(fmaf(d, waB, preB.y));
            waA = __shfl_sync(0xffffffffu, waA, m);
            wbA = __shfl_sync(0xffffffffu, wbA, m);
            waB = __shfl_sync(0xffffffffu, waB, m);
            wbB = __shfl_sync(0xffffffffu, wbB, m);

            float4 wa4 = sWW[(2*m)    *32 + lane];
            float4 wb4 = sWW[(2*m + 1)*32 + lane];
            preA.x = fmaf(wa4.x, waA, fmaf(wb4.x, wbA, preA.x));
            preA.y = fmaf(wa4.y, waA, fmaf(wb4.y, wbA, preA.y));
            tvA.x  = fmaf(wa4.z, waA, fmaf(wb4.z, wbA, tvA.x));
            tvA.y  = fmaf(wa4.w, waA, fmaf(wb4.w, wbA, tvA.y));
            preB.x = fmaf(wa4.x, waB, fmaf(wb4.x, wbB, preB.x));
            preB.y = fmaf(wa4.y, waB, fmaf(wb4.y, wbB, preB.y));
            tvB.x  = fmaf(wa4.z, waB, fmaf(wb4.z, wbB, tvB.x));
            tvB.y  = fmaf(wa4.w, waB, fmaf(wb4.w, wbB, tvB.y));

            float da = sD21[(2*m)*32 + lane], db = sD21[(2*m+1)*32 + lane];
            yaA = fmaf(da, waA, fmaf(db, wbA, yaA));
            yaB = fmaf(da, waB, fmaf(db, wbB, yaB));
        }
        tA = tvA; tB = tvB;
        // ---- y = (C2·Einv)·t_new + accumulated (D21 w + D22 u) ----
        #pragma unroll
        for (int k = 0; k < 64; k++) {
            float sa = (k & 1) ? tA.y : tA.x;
            float sb = (k & 1) ? tB.y : tB.x;
            float ta = __shfl_sync(0xffffffffu, sa, k >> 1);
            float tb = __shfl_sync(0xffffffffu, sb, k >> 1);
            float c = sYW[k*32 + lane];
            yaA = fmaf(c, ta, yaA); yaB = fmaf(c, tb, yaB);
        }
        oA[t * 32] = yaA;
        oB[t * 32] = yaB;
    }
}

// ---------------- launch ----------------
extern "C" void kernel_launch(void* const* d_in, const int* in_sizes, int n_in,
                              void* d_out, int out_size) {
    const float* u_in = (const float*)d_in[0];
    const float* X    = (const float*)d_in[1];
    const float* Y    = (const float*)d_in[2];
    const float* B2   = (const float*)d_in[3];
    const float* C2   = (const float*)d_in[4];
    const float* D21  = (const float*)d_in[5];
    const float* D22  = (const float*)d_in[6];
    const float* D12  = (const float*)d_in[7];
    float* out = (float*)d_out;

    (void)in_sizes; (void)n_in; (void)out_size;

    cudaFuncSetAttribute(ren_main, cudaFuncAttributeMaxDynamicSharedMemorySize, 102400);

    ren_precompute<<<32, 128>>>(X, Y, B2, C2, D21, D22, D12);
    ren_invert<<<1, 256>>>();
    ren_fuse<<<16, 256>>>();
    ren_main<<<128, 128, 102400>>>(u_in, out);
}